// round 8
// baseline (speedup 1.0000x reference)
#include <cuda_runtime.h>
#include <cuda_bf16.h>
#include <cstdint>

#define NN 200000
#define NE 400000
#define HS 128
#define ROW_TILES 1563            // ceil(200000/128)
#define NPAD (ROW_TILES * 128)    // 200064 padded rows

#define LDA 136                   // padded smem row stride (elems)
#define ASZ (128 * LDA)           // elems per smem tile buffer
#define TSZ (ASZ * 2)             // bytes per smem tile buffer (34816)
#define SMEM_MMA (6 * TSZ)        // k_mma: A hi/lo + B 2stage x hi/lo
#define LDS_S 130                 // fp32 staging row stride
#define SMEM_MMA2 (4 * TSZ + 128 * LDS_S * 4)  // A hi/lo + B hi/lo + S fp32

// ---------------- scratch (device globals; no allocs allowed) ----------------
// NOTE: never passed as kernel args from host (host shadow + ATS trap);
// all resolution happens inside device code via `sel`.
__device__ float g_xall[(size_t)NN * 512];   // x@[w_iou;w_f]^T + bias  [N,512] = i|o|u|xf
__device__ float g_hu[(size_t)NN * HS];      // h_child @ u_f^T         [N,128]
__device__ float g_hsum[(size_t)NN * HS];    // segsum(h_child[src])    [N,128]
__device__ float g_fcsum[(size_t)NN * HS];   // segsum(f*c_child[src])  [N,128]
// pre-split bf16 A operands (padded; tail rows stay zero from module-load init)
__device__ __align__(16) __nv_bfloat16 g_xhi[(size_t)NPAD * HS];
__device__ __align__(16) __nv_bfloat16 g_xlo[(size_t)NPAD * HS];
__device__ __align__(16) __nv_bfloat16 g_hhi[(size_t)NPAD * HS];
__device__ __align__(16) __nv_bfloat16 g_hlo[(size_t)NPAD * HS];
__device__ __align__(16) __nv_bfloat16 g_shi[(size_t)NPAD * HS];
__device__ __align__(16) __nv_bfloat16 g_slo[(size_t)NPAD * HS];
// packed bf16 weights, 8 tiles of [128 n][128 k] row-major:
// tiles 0-3: [w_iou;w_f] (512 rows): 0=i,1=o,2=u,3=f; 4-6: u_iou (4=i,5=o,6=u); 7: u_f
__device__ __align__(16) __nv_bfloat16 g_Bhi[8 * 16384];
__device__ __align__(16) __nv_bfloat16 g_Blo[8 * 16384];
__device__ __align__(16) float g_bias[512];

__device__ __forceinline__ float sigmoidf(float v) { return 1.0f / (1.0f + __expf(-v)); }

__device__ __forceinline__ uint32_t smem_u32(const void* p) {
    uint32_t a;
    asm("{ .reg .u64 t; cvta.to.shared.u64 t, %1; cvt.u32.u64 %0, t; }" : "=r"(a) : "l"(p));
    return a;
}

__device__ __forceinline__ void ldsm4(uint32_t* r, uint32_t addr) {
    asm volatile("ldmatrix.sync.aligned.m8n8.x4.shared.b16 {%0,%1,%2,%3}, [%4];"
                 : "=r"(r[0]), "=r"(r[1]), "=r"(r[2]), "=r"(r[3]) : "r"(addr));
}

__device__ __forceinline__ void mma16816(float* c, const uint32_t* a, uint32_t b0, uint32_t b1) {
    asm volatile(
        "mma.sync.aligned.m16n8k16.row.col.f32.bf16.bf16.f32 "
        "{%0,%1,%2,%3}, {%4,%5,%6,%7}, {%8,%9}, {%0,%1,%2,%3};"
        : "+f"(c[0]), "+f"(c[1]), "+f"(c[2]), "+f"(c[3])
        : "r"(a[0]), "r"(a[1]), "r"(a[2]), "r"(a[3]), "r"(b0), "r"(b1));
}

__device__ __forceinline__ void cp16(uint32_t dst, const void* src) {
    asm volatile("cp.async.cg.shared.global [%0], [%1], 16;" :: "r"(dst), "l"(src));
}
__device__ __forceinline__ void cp_commit() {
    asm volatile("cp.async.commit_group;");
}
template <int N>
__device__ __forceinline__ void cp_wait() {
    asm volatile("cp.async.wait_group %0;" :: "n"(N));
}

__device__ __forceinline__ void red4(float* p, float a, float b, float c, float d) {
    asm volatile("red.global.add.v4.f32 [%0], {%1,%2,%3,%4};"
                 :: "l"(p), "f"(a), "f"(b), "f"(c), "f"(d) : "memory");
}

__device__ __forceinline__ uint32_t pack2(__nv_bfloat16 lo, __nv_bfloat16 hi) {
    return (uint32_t)__bfloat16_as_ushort(lo) | ((uint32_t)__bfloat16_as_ushort(hi) << 16);
}

// ---------------- split fp32 -> bf16 hi/lo (4 elems per thread) ----------------
// sel 0: src=ext (x)       -> g_xhi/g_xlo   (+ zero g_hsum/g_fcsum)
// sel 1: src=ext (h_child) -> g_hhi/g_hlo
// sel 2: src=g_hsum        -> g_shi/g_slo
__global__ void k_split(const float* __restrict__ ext, int sel) {
    const int total4 = NN * HS / 4;
    int i = blockIdx.x * blockDim.x + threadIdx.x;
    if (i >= total4) return;
    const float* src = (sel == 2) ? g_hsum : ext;
    __nv_bfloat16* hi = (sel == 0) ? g_xhi : (sel == 1) ? g_hhi : g_shi;
    __nv_bfloat16* lo = (sel == 0) ? g_xlo : (sel == 1) ? g_hlo : g_slo;
    if (sel == 0) {
        float4 z = make_float4(0.f, 0.f, 0.f, 0.f);
        reinterpret_cast<float4*>(g_hsum)[i] = z;
        reinterpret_cast<float4*>(g_fcsum)[i] = z;
    }
    float4 v = reinterpret_cast<const float4*>(src)[i];
    float f[4] = {v.x, v.y, v.z, v.w};
    uint32_t hp[2], lp[2];
#pragma unroll
    for (int p = 0; p < 2; p++) {
        __nv_bfloat16 h0 = __float2bfloat16(f[2 * p]);
        __nv_bfloat16 h1 = __float2bfloat16(f[2 * p + 1]);
        __nv_bfloat16 l0 = __float2bfloat16(f[2 * p] - __bfloat162float(h0));
        __nv_bfloat16 l1 = __float2bfloat16(f[2 * p + 1] - __bfloat162float(h1));
        hp[p] = pack2(h0, h1);
        lp[p] = pack2(l0, l1);
    }
    reinterpret_cast<uint2*>(hi)[i] = make_uint2(hp[0], hp[1]);
    reinterpret_cast<uint2*>(lo)[i] = make_uint2(lp[0], lp[1]);
}

// ---------------- pack weights: fp32 -> bf16 hi/lo, row-major [n][k] tiles ----------------
__global__ void k_prep(const float* __restrict__ w_iou, const float* __restrict__ w_f,
                       const float* __restrict__ u_iou, const float* __restrict__ u_f,
                       const float* __restrict__ b_iou, const float* __restrict__ b_f) {
    int i = blockIdx.x * blockDim.x + threadIdx.x;
    if (i < 512) g_bias[i] = (i < 384) ? b_iou[i] : b_f[i - 384];
    if (i >= 131072) return;
    int n, k, tile;
    float val;
    if (i < 65536) {                       // [w_iou ; w_f], 512 rows
        n = i >> 7; k = i & 127;
        tile = n >> 7;
        val = (n < 384) ? w_iou[n * 128 + k] : w_f[(n - 384) * 128 + k];
    } else if (i < 65536 + 49152) {        // u_iou, 384 rows
        int j = i - 65536;
        n = j >> 7; k = j & 127;
        tile = 4 + (n >> 7);
        val = u_iou[n * 128 + k];
    } else {                               // u_f, 128 rows
        int j = i - 114688;
        n = j >> 7; k = j & 127;
        tile = 7;
        val = u_f[n * 128 + k];
    }
    __nv_bfloat16 hi = __float2bfloat16(val);
    __nv_bfloat16 lo = __float2bfloat16(val - __bfloat162float(hi));
    int off = tile * 16384 + (n & 127) * 128 + k;
    g_Bhi[off] = hi;
    g_Blo[off] = lo;
}

// copy one [128][128] bf16 tile, global row-major -> smem padded LDA, via cp.async
__device__ __forceinline__ void copy_tile(uint32_t sdst, const __nv_bfloat16* gsrc, int tid) {
#pragma unroll
    for (int it = 0; it < 8; it++) {
        int j = tid + it * 256;        // 2048 16B chunks
        int r = j >> 4, c = j & 15;
        cp16(sdst + (uint32_t)(r * LDA + c * 8) * 2, gsrc + r * 128 + c * 8);
    }
}

// ---- shared MMA inner loop: 3-term split over resident smem tiles ----
// acc[2][8][4], warp tile 32x64. aHiB/aLoB/bHiB/bLoB = per-lane smem byte addrs.
__device__ __forceinline__ void mma_tile(float acc[2][8][4], uint32_t aHiB, uint32_t aLoB,
                                         uint32_t bHiB, uint32_t bLoB) {
#pragma unroll
    for (int i = 0; i < 2; i++)
#pragma unroll
        for (int j = 0; j < 8; j++)
#pragma unroll
            for (int q = 0; q < 4; q++) acc[i][j][q] = 0.f;
#pragma unroll
    for (int t3 = 0; t3 < 3; t3++) {
        const uint32_t aBase = (t3 == 2) ? aLoB : aHiB;
        const uint32_t bBase = (t3 == 1) ? bLoB : bHiB;
#pragma unroll
        for (int kb = 0; kb < 8; kb++) {
            uint32_t a[2][4];
            ldsm4(a[0], aBase + kb * 32);
            ldsm4(a[1], aBase + 16 * LDA * 2 + kb * 32);
            uint32_t b[4][4];
#pragma unroll
            for (int p = 0; p < 4; p++)
                ldsm4(b[p], bBase + p * 16 * LDA * 2 + kb * 32);
#pragma unroll
            for (int i = 0; i < 2; i++)
#pragma unroll
                for (int j = 0; j < 8; j++)
                    mma16816(acc[i][j], a[i], b[j >> 1][(j & 1) * 2], b[j >> 1][(j & 1) * 2 + 1]);
        }
    }
}

// ============================================================================
// k_mma (R6-proven): A row tile resident, loop over output column tiles,
// double-buffered B. sel 0: x -> g_xall (4 tiles, +bias). sel 1: h -> g_hu.
// ============================================================================
__global__ void __launch_bounds__(256) k_mma(int sel) {
    const __nv_bfloat16* Ahi = (sel == 0) ? g_xhi : g_hhi;
    const __nv_bfloat16* Alo = (sel == 0) ? g_xlo : g_hlo;
    float* out = (sel == 0) ? g_xall : g_hu;
    const int ostride = (sel == 0) ? 512 : 128;
    const int first   = (sel == 0) ? 0 : 7;
    const int ntiles  = (sel == 0) ? 4 : 1;
    const int usebias = (sel == 0);

    extern __shared__ __nv_bfloat16 sm[];
    const int tid = threadIdx.x;
    const int lane = tid & 31, wid = tid >> 5;
    const int brow = blockIdx.x * 128;

    const uint32_t sA32 = smem_u32(sm);
    const uint32_t sB32 = sA32 + 2 * TSZ;

    copy_tile(sA32, Ahi + (size_t)brow * 128, tid);
    copy_tile(sA32 + TSZ, Alo + (size_t)brow * 128, tid);
    copy_tile(sB32, g_Bhi + (size_t)first * 16384, tid);
    copy_tile(sB32 + TSZ, g_Blo + (size_t)first * 16384, tid);
    cp_commit();

    const int wr = wid & 3;
    const int wcol = wid >> 2;
    const int aRow = wr * 32 + (lane & 15);
    const int aK   = (lane >> 4) * 8;
    const int gg   = lane >> 3;
    const int bRow = wcol * 64 + (gg >> 1) * 8 + (lane & 7);
    const int bK   = (gg & 1) * 8;
    const uint32_t aHiB = sA32 + (uint32_t)(aRow * LDA + aK) * 2;
    const uint32_t aLoB = aHiB + TSZ;
    const uint32_t bOffB = (uint32_t)(bRow * LDA + bK) * 2;

    for (int t = 0; t < ntiles; t++) {
        if (t + 1 < ntiles) {
            uint32_t st = ((t + 1) & 1) ? (sB32 + 2 * TSZ) : sB32;
            copy_tile(st, g_Bhi + (size_t)(first + t + 1) * 16384, tid);
            copy_tile(st + TSZ, g_Blo + (size_t)(first + t + 1) * 16384, tid);
            cp_commit();
            cp_wait<1>();
        } else {
            cp_wait<0>();
        }
        __syncthreads();

        const uint32_t stage = (t & 1) ? (sB32 + 2 * TSZ) : sB32;
        float acc[2][8][4];
        mma_tile(acc, aHiB, aLoB, stage + bOffB, stage + bOffB + TSZ);

        const int colb = t * 128 + wcol * 64;
#pragma unroll
        for (int i = 0; i < 2; i++) {
            int row0 = brow + wr * 32 + i * 16 + (lane >> 2);
            int row1 = row0 + 8;
#pragma unroll
            for (int j = 0; j < 8; j++) {
                int col = colb + j * 8 + (lane & 3) * 2;
                float bx = 0.f, by = 0.f;
                if (usebias) { bx = g_bias[col]; by = g_bias[col + 1]; }
                if (row0 < NN) {
                    float2 v = make_float2(acc[i][j][0] + bx, acc[i][j][1] + by);
                    *reinterpret_cast<float2*>(out + (size_t)row0 * ostride + col) = v;
                }
                if (row1 < NN) {
                    float2 v = make_float2(acc[i][j][2] + bx, acc[i][j][3] + by);
                    *reinterpret_cast<float2*>(out + (size_t)row1 * ostride + col) = v;
                }
            }
        }
        __syncthreads();
    }
}

// ============================================================================
// k_mma2: hsum GEMM fused with node update. CTA = 128-row tile; loops gates
// in order i (btile 4, xall col 0), u (btile 6, xall col 256), o (btile 5,
// xall col 128). Stages sigma(i-pre) then c in fp32 smem S. Writes h,c to out.
// uhsum never hits gmem.
// ============================================================================
__global__ void __launch_bounds__(256) k_mma2(float* __restrict__ out) {
    extern __shared__ __nv_bfloat16 sm[];
    const int tid = threadIdx.x;
    const int lane = tid & 31, wid = tid >> 5;
    const int brow = blockIdx.x * 128;

    const uint32_t sA32 = smem_u32(sm);
    const uint32_t sB32 = sA32 + 2 * TSZ;
    float* S = reinterpret_cast<float*>(reinterpret_cast<char*>(sm) + 4 * TSZ);

    const int BT[3]   = {4, 6, 5};       // btiles: i, u, o
    const int XOFF[3] = {0, 256, 128};   // xall col offsets: i, u, o

    // prologue: A (hsum hi/lo) + B gate i
    copy_tile(sA32, g_shi + (size_t)brow * 128, tid);
    copy_tile(sA32 + TSZ, g_slo + (size_t)brow * 128, tid);
    copy_tile(sB32, g_Bhi + (size_t)BT[0] * 16384, tid);
    copy_tile(sB32 + TSZ, g_Blo + (size_t)BT[0] * 16384, tid);
    cp_commit();

    const int wr = wid & 3;
    const int wcol = wid >> 2;
    const int aRow = wr * 32 + (lane & 15);
    const int aK   = (lane >> 4) * 8;
    const int gg   = lane >> 3;
    const int bRow = wcol * 64 + (gg >> 1) * 8 + (lane & 7);
    const int bK   = (gg & 1) * 8;
    const uint32_t aHiB = sA32 + (uint32_t)(aRow * LDA + aK) * 2;
    const uint32_t aLoB = aHiB + TSZ;
    const uint32_t bHiB = sB32 + (uint32_t)(bRow * LDA + bK) * 2;
    const uint32_t bLoB = bHiB + TSZ;

    for (int g = 0; g < 3; g++) {
        cp_wait<0>();
        __syncthreads();                 // B[g] (and A) ready; S from prev epi visible

        float acc[2][8][4];
        mma_tile(acc, aHiB, aLoB, bHiB, bLoB);

        __syncthreads();                 // all warps done reading B[g]
        if (g + 1 < 3) {                 // overlap next-B transfer with epilogue
            copy_tile(sB32, g_Bhi + (size_t)BT[g + 1] * 16384, tid);
            copy_tile(sB32 + TSZ, g_Blo + (size_t)BT[g + 1] * 16384, tid);
            cp_commit();
        }

        const int xoff = XOFF[g];
        const int colb = wcol * 64;
#pragma unroll
        for (int i = 0; i < 2; i++) {
            int r0 = wr * 32 + i * 16 + (lane >> 2);   // local row in tile
            int r1 = r0 + 8;
#pragma unroll
            for (int j = 0; j < 8; j++) {
                int col = colb + j * 8 + (lane & 3) * 2;
#pragma unroll
                for (int h2 = 0; h2 < 2; h2++) {
                    int rl = h2 ? r1 : r0;
                    int grow = brow + rl;
                    float a0 = acc[i][j][h2 * 2], a1 = acc[i][j][h2 * 2 + 1];
                    if (grow < NN) {
                        const float* xr = g_xall + (size_t)grow * 512 + xoff + col;
                        float p0 = a0 + xr[0];
                        float p1 = a1 + xr[1];
                        if (g == 0) {                     // i gate: stage sigma(i)
                            S[rl * LDS_S + col]     = sigmoidf(p0);
                            S[rl * LDS_S + col + 1] = sigmoidf(p1);
                        } else if (g == 1) {              // u gate: c = sig(i)*tanh(u)+fc
                            const float* fr = g_fcsum + (size_t)grow * 128 + col;
                            float c0 = S[rl * LDS_S + col]     * tanhf(p0) + fr[0];
                            float c1 = S[rl * LDS_S + col + 1] * tanhf(p1) + fr[1];
                            *reinterpret_cast<float2*>(out + (size_t)NN * 128 +
                                                       (size_t)grow * 128 + col) =
                                make_float2(c0, c1);
                            S[rl * LDS_S + col]     = c0;
                            S[rl * LDS_S + col + 1] = c1;
                        } else {                          // o gate: h = sig(o)*tanh(c)
                            float h0 = sigmoidf(p0) * tanhf(S[rl * LDS_S + col]);
                            float h1 = sigmoidf(p1) * tanhf(S[rl * LDS_S + col + 1]);
                            *reinterpret_cast<float2*>(out + (size_t)grow * 128 + col) =
                                make_float2(h0, h1);
                        }
                    }
                }
            }
        }
        __syncthreads();                 // epi done before next loop's B-wait reuse
    }
}

// ---------------- edge pass: one warp per edge, vector red atomics ----------------
__global__ void k_edge(const float* __restrict__ h_child, const float* __restrict__ c_child,
                       const int* __restrict__ esrc, const int* __restrict__ edst) {
    int idx = blockIdx.x * blockDim.x + threadIdx.x;
    int e = idx >> 5;
    int q = idx & 31;
    if (e >= NE) return;
    int s = esrc[e];
    int d = edst[e];
    float4 h4  = reinterpret_cast<const float4*>(h_child + (size_t)s * HS)[q];
    float4 hu4 = reinterpret_cast<const float4*>(g_hu + (size_t)s * HS)[q];
    float4 c4  = reinterpret_cast<const float4*>(c_child + (size_t)s * HS)[q];
    float4 xf4 = reinterpret_cast<const float4*>(g_xall + (size_t)d * 512 + 384)[q];
    red4(g_hsum + (size_t)d * HS + q * 4, h4.x, h4.y, h4.z, h4.w);
    red4(g_fcsum + (size_t)d * HS + q * 4,
         sigmoidf(xf4.x + hu4.x) * c4.x,
         sigmoidf(xf4.y + hu4.y) * c4.y,
         sigmoidf(xf4.z + hu4.z) * c4.z,
         sigmoidf(xf4.w + hu4.w) * c4.w);
}

// ============================================================================
extern "C" void kernel_launch(void* const* d_in, const int* in_sizes, int n_in,
                              void* d_out, int out_size) {
    const float* x       = (const float*)d_in[0];
    const float* h_child = (const float*)d_in[1];
    const float* c_child = (const float*)d_in[2];
    const float* w_iou   = (const float*)d_in[3];
    const float* b_iou   = (const float*)d_in[4];
    const float* w_f     = (const float*)d_in[5];
    const float* b_f     = (const float*)d_in[6];
    const float* u_iou   = (const float*)d_in[7];
    const float* u_f     = (const float*)d_in[8];
    const int*   esrc    = (const int*)d_in[9];
    const int*   edst    = (const int*)d_in[10];
    float* out = (float*)d_out;

    static bool configured = false;
    if (!configured) {
        cudaFuncSetAttribute(k_mma, cudaFuncAttributeMaxDynamicSharedMemorySize, SMEM_MMA);
        cudaFuncSetAttribute(k_mma2, cudaFuncAttributeMaxDynamicSharedMemorySize, SMEM_MMA2);
        configured = true;
    }

    const int total4 = NN * HS / 4;
    const int sgrid = (total4 + 255) / 256;

    k_prep<<<131072 / 256, 256>>>(w_iou, w_f, u_iou, u_f, b_iou, b_f);
    k_split<<<sgrid, 256>>>(x, 0);          // also zeroes g_hsum/g_fcsum
    k_split<<<sgrid, 256>>>(h_child, 1);
    k_mma<<<ROW_TILES, 256, SMEM_MMA>>>(0); // x -> g_xall (i|o|u|xf)
    k_mma<<<ROW_TILES, 256, SMEM_MMA>>>(1); // h_child -> g_hu
    k_edge<<<(NE * 32) / 256, 256>>>(h_child, c_child, esrc, edst);
    k_split<<<sgrid, 256>>>(nullptr, 2);    // g_hsum -> g_shi/g_slo
    k_mma2<<<ROW_TILES, 256, SMEM_MMA2>>>(out);  // fused uh GEMM + node update
}

// round 9
// speedup vs baseline: 1.0701x; 1.0701x over previous
#include <cuda_runtime.h>
#include <cuda_bf16.h>
#include <cstdint>

#define NN 200000
#define NE 400000
#define HS 128
#define ROW_TILES 1563            // ceil(200000/128)
#define NPAD (ROW_TILES * 128)    // 200064 padded rows

#define LDA 136                   // padded smem row stride (elems)
#define ASZ (128 * LDA)           // elems per smem tile buffer
#define TSZ (ASZ * 2)             // bytes per smem tile buffer (34816)
#define SMEM_MMA (6 * TSZ)        // A hi/lo + B 2stage x hi/lo = 208896 B

// ---------------- scratch (device globals; no allocs allowed) ----------------
// NOTE: never passed as kernel args from host (host shadow + ATS trap);
// all resolution happens inside device code via `sel`.
__device__ float g_xall[(size_t)NN * 512];   // x@[w_iou;w_f]^T + bias  [N,512] = i|o|u|xf
__device__ float g_hu[(size_t)NN * HS];      // h_child @ u_f^T         [N,128]
__device__ float g_hsum[(size_t)NN * HS];    // segsum(h_child[src])    [N,128]
__device__ float g_fcsum[(size_t)NN * HS];   // segsum(f*c_child[src])  [N,128]
__device__ float g_uhsum[(size_t)NN * 384];  // hsum @ u_iou^T          [N,384]
// pre-split bf16 A operands (padded; tail rows stay zero from module-load init)
__device__ __align__(16) __nv_bfloat16 g_xhi[(size_t)NPAD * HS];
__device__ __align__(16) __nv_bfloat16 g_xlo[(size_t)NPAD * HS];
__device__ __align__(16) __nv_bfloat16 g_hhi[(size_t)NPAD * HS];
__device__ __align__(16) __nv_bfloat16 g_hlo[(size_t)NPAD * HS];
__device__ __align__(16) __nv_bfloat16 g_shi[(size_t)NPAD * HS];
__device__ __align__(16) __nv_bfloat16 g_slo[(size_t)NPAD * HS];
// packed bf16 weights, 8 tiles of [128 n][128 k] row-major:
// tiles 0-3: [w_iou;w_f] (512 rows), 4-6: u_iou (384), 7: u_f (128)
__device__ __align__(16) __nv_bfloat16 g_Bhi[8 * 16384];
__device__ __align__(16) __nv_bfloat16 g_Blo[8 * 16384];
__device__ __align__(16) float g_bias[512];

__device__ __forceinline__ float sigmoidf(float v) { return 1.0f / (1.0f + __expf(-v)); }

__device__ __forceinline__ uint32_t smem_u32(const void* p) {
    uint32_t a;
    asm("{ .reg .u64 t; cvta.to.shared.u64 t, %1; cvt.u32.u64 %0, t; }" : "=r"(a) : "l"(p));
    return a;
}

__device__ __forceinline__ void ldsm4(uint32_t* r, uint32_t addr) {
    asm volatile("ldmatrix.sync.aligned.m8n8.x4.shared.b16 {%0,%1,%2,%3}, [%4];"
                 : "=r"(r[0]), "=r"(r[1]), "=r"(r[2]), "=r"(r[3]) : "r"(addr));
}

__device__ __forceinline__ void mma16816(float* c, const uint32_t* a, uint32_t b0, uint32_t b1) {
    asm volatile(
        "mma.sync.aligned.m16n8k16.row.col.f32.bf16.bf16.f32 "
        "{%0,%1,%2,%3}, {%4,%5,%6,%7}, {%8,%9}, {%0,%1,%2,%3};"
        : "+f"(c[0]), "+f"(c[1]), "+f"(c[2]), "+f"(c[3])
        : "r"(a[0]), "r"(a[1]), "r"(a[2]), "r"(a[3]), "r"(b0), "r"(b1));
}

__device__ __forceinline__ void cp16(uint32_t dst, const void* src) {
    asm volatile("cp.async.cg.shared.global [%0], [%1], 16;" :: "r"(dst), "l"(src));
}
__device__ __forceinline__ void cp_commit() {
    asm volatile("cp.async.commit_group;");
}
template <int N>
__device__ __forceinline__ void cp_wait() {
    asm volatile("cp.async.wait_group %0;" :: "n"(N));
}

__device__ __forceinline__ uint32_t pack2(__nv_bfloat16 lo, __nv_bfloat16 hi) {
    return (uint32_t)__bfloat16_as_ushort(lo) | ((uint32_t)__bfloat16_as_ushort(hi) << 16);
}

// ---------------- split fp32 -> bf16 hi/lo (4 elems per thread) ----------------
// sel 0: src=ext (x)       -> g_xhi/g_xlo   (+ zero g_hsum/g_fcsum)
// sel 1: src=ext (h_child) -> g_hhi/g_hlo
// sel 2: src=g_hsum        -> g_shi/g_slo
__global__ void k_split(const float* __restrict__ ext, int sel) {
    const int total4 = NN * HS / 4;
    int i = blockIdx.x * blockDim.x + threadIdx.x;
    if (i >= total4) return;
    const float* src = (sel == 2) ? g_hsum : ext;
    __nv_bfloat16* hi = (sel == 0) ? g_xhi : (sel == 1) ? g_hhi : g_shi;
    __nv_bfloat16* lo = (sel == 0) ? g_xlo : (sel == 1) ? g_hlo : g_slo;
    if (sel == 0) {
        float4 z = make_float4(0.f, 0.f, 0.f, 0.f);
        reinterpret_cast<float4*>(g_hsum)[i] = z;
        reinterpret_cast<float4*>(g_fcsum)[i] = z;
    }
    float4 v = reinterpret_cast<const float4*>(src)[i];
    float f[4] = {v.x, v.y, v.z, v.w};
    uint32_t hp[2], lp[2];
#pragma unroll
    for (int p = 0; p < 2; p++) {
        __nv_bfloat16 h0 = __float2bfloat16(f[2 * p]);
        __nv_bfloat16 h1 = __float2bfloat16(f[2 * p + 1]);
        __nv_bfloat16 l0 = __float2bfloat16(f[2 * p] - __bfloat162float(h0));
        __nv_bfloat16 l1 = __float2bfloat16(f[2 * p + 1] - __bfloat162float(h1));
        hp[p] = pack2(h0, h1);
        lp[p] = pack2(l0, l1);
    }
    reinterpret_cast<uint2*>(hi)[i] = make_uint2(hp[0], hp[1]);
    reinterpret_cast<uint2*>(lo)[i] = make_uint2(lp[0], lp[1]);
}

// ---------------- pack weights: fp32 -> bf16 hi/lo, row-major [n][k] tiles ----------------
__global__ void k_prep(const float* __restrict__ w_iou, const float* __restrict__ w_f,
                       const float* __restrict__ u_iou, const float* __restrict__ u_f,
                       const float* __restrict__ b_iou, const float* __restrict__ b_f) {
    int i = blockIdx.x * blockDim.x + threadIdx.x;
    if (i < 512) g_bias[i] = (i < 384) ? b_iou[i] : b_f[i - 384];
    if (i >= 131072) return;
    int n, k, tile;
    float val;
    if (i < 65536) {                       // [w_iou ; w_f], 512 rows
        n = i >> 7; k = i & 127;
        tile = n >> 7;
        val = (n < 384) ? w_iou[n * 128 + k] : w_f[(n - 384) * 128 + k];
    } else if (i < 65536 + 49152) {        // u_iou, 384 rows
        int j = i - 65536;
        n = j >> 7; k = j & 127;
        tile = 4 + (n >> 7);
        val = u_iou[n * 128 + k];
    } else {                               // u_f, 128 rows
        int j = i - 114688;
        n = j >> 7; k = j & 127;
        tile = 7;
        val = u_f[n * 128 + k];
    }
    __nv_bfloat16 hi = __float2bfloat16(val);
    __nv_bfloat16 lo = __float2bfloat16(val - __bfloat162float(hi));
    int off = tile * 16384 + (n & 127) * 128 + k;
    g_Bhi[off] = hi;
    g_Blo[off] = lo;
}

// copy one [128][128] bf16 tile, global row-major -> smem padded LDA, via cp.async
// NT = threads participating (must divide 2048)
template <int NT>
__device__ __forceinline__ void copy_tile(uint32_t sdst, const __nv_bfloat16* gsrc, int tid) {
#pragma unroll
    for (int it = 0; it < 2048 / NT; it++) {
        int j = tid + it * NT;        // 2048 16B chunks
        int r = j >> 4, c = j & 15;
        cp16(sdst + (uint32_t)(r * LDA + c * 8) * 2, gsrc + r * 128 + c * 8);
    }
}

// ============================================================================
// bf16 mma.sync GEMM, 512 threads / 16 warps (4 per SMSP for latency hiding).
// A row tile [128,128] resident in smem; loop over output column tiles with
// double-buffered B. Warp grid 4x4; warp tile 32 rows x 32 cols (acc 32 regs).
// 3-term split: Ahi*Bhi + Ahi*Blo + Alo*Bhi.
// sel 0: A=x_hi/lo -> g_xall  (4 tiles, +bias). sel 1: h -> g_hu. sel 2: hsum -> g_uhsum.
// ============================================================================
__global__ void __launch_bounds__(512) k_mma(int sel) {
    const __nv_bfloat16* Ahi = (sel == 0) ? g_xhi : (sel == 1) ? g_hhi : g_shi;
    const __nv_bfloat16* Alo = (sel == 0) ? g_xlo : (sel == 1) ? g_hlo : g_slo;
    float* out = (sel == 0) ? g_xall : (sel == 1) ? g_hu : g_uhsum;
    const int ostride = (sel == 0) ? 512 : (sel == 1) ? 128 : 384;
    const int first   = (sel == 0) ? 0 : (sel == 1) ? 7 : 4;
    const int ntiles  = (sel == 0) ? 4 : (sel == 1) ? 1 : 3;
    const int usebias = (sel == 0);

    extern __shared__ __nv_bfloat16 sm[];
    const int tid = threadIdx.x;
    const int lane = tid & 31, wid = tid >> 5;
    const int brow = blockIdx.x * 128;

    const uint32_t sA32 = smem_u32(sm);
    const uint32_t sB32 = sA32 + 2 * TSZ;

    copy_tile<512>(sA32, Ahi + (size_t)brow * 128, tid);
    copy_tile<512>(sA32 + TSZ, Alo + (size_t)brow * 128, tid);
    copy_tile<512>(sB32, g_Bhi + (size_t)first * 16384, tid);
    copy_tile<512>(sB32 + TSZ, g_Blo + (size_t)first * 16384, tid);
    cp_commit();

    // ---- warp tiling: 4x4 warps, each 32 rows x 32 cols ----
    const int wr = wid & 3;        // row group 0..3
    const int wc = wid >> 2;       // col group 0..3
    const int aRow = wr * 32 + (lane & 15);
    const int aK   = (lane >> 4) * 8;
    const int gg   = lane >> 3;
    const int bRow = wc * 32 + (gg >> 1) * 8 + (lane & 7);   // 16 cols per ldsm4
    const int bK   = (gg & 1) * 8;
    const uint32_t aHiB = sA32 + (uint32_t)(aRow * LDA + aK) * 2;
    const uint32_t aLoB = aHiB + TSZ;
    const uint32_t bOffB = (uint32_t)(bRow * LDA + bK) * 2;

    for (int t = 0; t < ntiles; t++) {
        if (t + 1 < ntiles) {
            uint32_t st = ((t + 1) & 1) ? (sB32 + 2 * TSZ) : sB32;
            copy_tile<512>(st, g_Bhi + (size_t)(first + t + 1) * 16384, tid);
            copy_tile<512>(st + TSZ, g_Blo + (size_t)(first + t + 1) * 16384, tid);
            cp_commit();
            cp_wait<1>();
        } else {
            cp_wait<0>();
        }
        __syncthreads();

        const uint32_t stage = (t & 1) ? (sB32 + 2 * TSZ) : sB32;
        const uint32_t bHiB = stage + bOffB;
        const uint32_t bLoB = bHiB + TSZ;

        float acc[2][4][4];
#pragma unroll
        for (int i = 0; i < 2; i++)
#pragma unroll
            for (int j = 0; j < 4; j++)
#pragma unroll
                for (int q = 0; q < 4; q++) acc[i][j][q] = 0.f;

#pragma unroll
        for (int t3 = 0; t3 < 3; t3++) {
            const uint32_t aBase = (t3 == 2) ? aLoB : aHiB;
            const uint32_t bBase = (t3 == 1) ? bLoB : bHiB;
#pragma unroll
            for (int kb = 0; kb < 8; kb++) {
                uint32_t a[2][4];
                ldsm4(a[0], aBase + kb * 32);
                ldsm4(a[1], aBase + 16 * LDA * 2 + kb * 32);
                uint32_t b[2][4];
#pragma unroll
                for (int p = 0; p < 2; p++)
                    ldsm4(b[p], bBase + p * 16 * LDA * 2 + kb * 32);
#pragma unroll
                for (int i = 0; i < 2; i++)
#pragma unroll
                    for (int j = 0; j < 4; j++)
                        mma16816(acc[i][j], a[i], b[j >> 1][(j & 1) * 2], b[j >> 1][(j & 1) * 2 + 1]);
            }
        }

        // ---- epilogue for this column tile ----
        const int colb = t * 128 + wc * 32;
#pragma unroll
        for (int i = 0; i < 2; i++) {
            int row0 = brow + wr * 32 + i * 16 + (lane >> 2);
            int row1 = row0 + 8;
#pragma unroll
            for (int j = 0; j < 4; j++) {
                int col = colb + j * 8 + (lane & 3) * 2;
                float bx = 0.f, by = 0.f;
                if (usebias) { bx = g_bias[col]; by = g_bias[col + 1]; }
                if (row0 < NN) {
                    float2 v = make_float2(acc[i][j][0] + bx, acc[i][j][1] + by);
                    *reinterpret_cast<float2*>(out + (size_t)row0 * ostride + col) = v;
                }
                if (row1 < NN) {
                    float2 v = make_float2(acc[i][j][2] + bx, acc[i][j][3] + by);
                    *reinterpret_cast<float2*>(out + (size_t)row1 * ostride + col) = v;
                }
            }
        }
        __syncthreads();
    }
}

// ---------------- edge pass: one warp per edge, scalar atomics (R6-proven) ----------------
__global__ void k_edge(const float* __restrict__ h_child, const float* __restrict__ c_child,
                       const int* __restrict__ esrc, const int* __restrict__ edst) {
    int idx = blockIdx.x * blockDim.x + threadIdx.x;
    int e = idx >> 5;
    int q = idx & 31;
    if (e >= NE) return;
    int s = esrc[e];
    int d = edst[e];
    float4 h4  = reinterpret_cast<const float4*>(h_child + (size_t)s * HS)[q];
    float4 hu4 = reinterpret_cast<const float4*>(g_hu + (size_t)s * HS)[q];
    float4 c4  = reinterpret_cast<const float4*>(c_child + (size_t)s * HS)[q];
    float4 xf4 = reinterpret_cast<const float4*>(g_xall + (size_t)d * 512 + 384)[q];
    float* hs = g_hsum + (size_t)d * HS + q * 4;
    float* fc = g_fcsum + (size_t)d * HS + q * 4;
    atomicAdd(hs + 0, h4.x); atomicAdd(hs + 1, h4.y);
    atomicAdd(hs + 2, h4.z); atomicAdd(hs + 3, h4.w);
    atomicAdd(fc + 0, sigmoidf(xf4.x + hu4.x) * c4.x);
    atomicAdd(fc + 1, sigmoidf(xf4.y + hu4.y) * c4.y);
    atomicAdd(fc + 2, sigmoidf(xf4.z + hu4.z) * c4.z);
    atomicAdd(fc + 3, sigmoidf(xf4.w + hu4.w) * c4.w);
}

// ---------------- final node update (R6-proven) ----------------
__global__ void k_final(float* __restrict__ out) {
    int idx = blockIdx.x * blockDim.x + threadIdx.x;
    if (idx >= NN * HS) return;
    int n = idx >> 7;
    int j = idx & 127;
    size_t bx = (size_t)n * 512;
    size_t bu = (size_t)n * 384;
    float i_ = sigmoidf(g_xall[bx + j]       + g_uhsum[bu + j]);
    float o_ = sigmoidf(g_xall[bx + 128 + j] + g_uhsum[bu + 128 + j]);
    float u_ = tanhf(   g_xall[bx + 256 + j] + g_uhsum[bu + 256 + j]);
    float c = i_ * u_ + g_fcsum[idx];
    float h = o_ * tanhf(c);
    out[idx] = h;
    out[(size_t)NN * HS + idx] = c;
}

// ============================================================================
extern "C" void kernel_launch(void* const* d_in, const int* in_sizes, int n_in,
                              void* d_out, int out_size) {
    const float* x       = (const float*)d_in[0];
    const float* h_child = (const float*)d_in[1];
    const float* c_child = (const float*)d_in[2];
    const float* w_iou   = (const float*)d_in[3];
    const float* b_iou   = (const float*)d_in[4];
    const float* w_f     = (const float*)d_in[5];
    const float* b_f     = (const float*)d_in[6];
    const float* u_iou   = (const float*)d_in[7];
    const float* u_f     = (const float*)d_in[8];
    const int*   esrc    = (const int*)d_in[9];
    const int*   edst    = (const int*)d_in[10];
    float* out = (float*)d_out;

    static bool configured = false;
    if (!configured) {
        cudaFuncSetAttribute(k_mma, cudaFuncAttributeMaxDynamicSharedMemorySize, SMEM_MMA);
        configured = true;
    }

    const int total4 = NN * HS / 4;
    const int sgrid = (total4 + 255) / 256;

    k_prep<<<131072 / 256, 256>>>(w_iou, w_f, u_iou, u_f, b_iou, b_f);
    k_split<<<sgrid, 256>>>(x, 0);            // also zeroes g_hsum/g_fcsum
    k_split<<<sgrid, 256>>>(h_child, 1);
    k_mma<<<ROW_TILES, 512, SMEM_MMA>>>(0);   // x -> g_xall (i|o|u|xf)
    k_mma<<<ROW_TILES, 512, SMEM_MMA>>>(1);   // h_child -> g_hu
    k_edge<<<(NE * 32) / 256, 256>>>(h_child, c_child, esrc, edst);
    k_split<<<sgrid, 256>>>(nullptr, 2);      // g_hsum -> g_shi/g_slo
    k_mma<<<ROW_TILES, 512, SMEM_MMA>>>(2);   // g_hsum -> g_uhsum
    k_final<<<(NN * HS + 255) / 256, 256>>>(out);
}

// round 10
// speedup vs baseline: 1.3073x; 1.2217x over previous
#include <cuda_runtime.h>
#include <cuda_fp16.h>
#include <cstdint>

#define NN 200000
#define NE 400000
#define HS 128
#define ROW_TILES 1563            // ceil(200000/128)
#define NPAD (ROW_TILES * 128)    // 200064 padded rows

#define LDA 136                   // padded smem row stride (elems)
#define ASZ (128 * LDA)           // elems per smem tile buffer
#define TSZ (ASZ * 2)             // bytes per smem tile buffer (34816)
#define SMEM_MMA (4 * TSZ)        // A hi/lo + B 2 stages = 139264 B

// ---------------- scratch (device globals; no allocs allowed) ----------------
// NOTE: never passed as kernel args from host (host shadow + ATS trap);
// all resolution happens inside device code via `sel`.
__device__ float g_xall[(size_t)NN * 512];   // x@[w_iou;w_f]^T + bias  [N,512] = i|o|u|xf
__device__ float g_hu[(size_t)NN * HS];      // h_child @ u_f^T         [N,128]
__device__ float g_hsum[(size_t)NN * HS];    // segsum(h_child[src])    [N,128]
__device__ float g_fcsum[(size_t)NN * HS];   // segsum(f*c_child[src])  [N,128]
__device__ float g_uhsum[(size_t)NN * 384];  // hsum @ u_iou^T          [N,384]
// pre-split fp16 A operands: A = hi + lo (22-bit effective mantissa)
__device__ __align__(16) __half g_xhi[(size_t)NPAD * HS];
__device__ __align__(16) __half g_xlo[(size_t)NPAD * HS];
__device__ __align__(16) __half g_hhi[(size_t)NPAD * HS];
__device__ __align__(16) __half g_hlo[(size_t)NPAD * HS];
__device__ __align__(16) __half g_shi[(size_t)NPAD * HS];
__device__ __align__(16) __half g_slo[(size_t)NPAD * HS];
// packed fp16 weights (hi only), 8 tiles of [128 n][128 k] row-major:
// tiles 0-3: [w_iou;w_f] (512 rows), 4-6: u_iou (384), 7: u_f (128)
__device__ __align__(16) __half g_Bhi[8 * 16384];
__device__ __align__(16) float g_bias[512];

__device__ __forceinline__ float sigmoidf(float v) { return 1.0f / (1.0f + __expf(-v)); }

__device__ __forceinline__ uint32_t smem_u32(const void* p) {
    uint32_t a;
    asm("{ .reg .u64 t; cvta.to.shared.u64 t, %1; cvt.u32.u64 %0, t; }" : "=r"(a) : "l"(p));
    return a;
}

__device__ __forceinline__ void ldsm4(uint32_t* r, uint32_t addr) {
    asm volatile("ldmatrix.sync.aligned.m8n8.x4.shared.b16 {%0,%1,%2,%3}, [%4];"
                 : "=r"(r[0]), "=r"(r[1]), "=r"(r[2]), "=r"(r[3]) : "r"(addr));
}

__device__ __forceinline__ void mma16816(float* c, const uint32_t* a, uint32_t b0, uint32_t b1) {
    asm volatile(
        "mma.sync.aligned.m16n8k16.row.col.f32.f16.f16.f32 "
        "{%0,%1,%2,%3}, {%4,%5,%6,%7}, {%8,%9}, {%0,%1,%2,%3};"
        : "+f"(c[0]), "+f"(c[1]), "+f"(c[2]), "+f"(c[3])
        : "r"(a[0]), "r"(a[1]), "r"(a[2]), "r"(a[3]), "r"(b0), "r"(b1));
}

__device__ __forceinline__ void cp16(uint32_t dst, const void* src) {
    asm volatile("cp.async.cg.shared.global [%0], [%1], 16;" :: "r"(dst), "l"(src));
}
__device__ __forceinline__ void cp_commit() {
    asm volatile("cp.async.commit_group;");
}
template <int N>
__device__ __forceinline__ void cp_wait() {
    asm volatile("cp.async.wait_group %0;" :: "n"(N));
}

__device__ __forceinline__ uint32_t pack2h(__half lo, __half hi) {
    return (uint32_t)__half_as_ushort(lo) | ((uint32_t)__half_as_ushort(hi) << 16);
}

// ---------------- split fp32 -> fp16 hi/lo (4 elems per thread) ----------------
// sel 0: src=ext (x)       -> g_xhi/g_xlo   (+ zero g_hsum/g_fcsum)
// sel 1: src=ext (h_child) -> g_hhi/g_hlo
// sel 2: src=g_hsum        -> g_shi/g_slo
__global__ void k_split(const float* __restrict__ ext, int sel) {
    const int total4 = NN * HS / 4;
    int i = blockIdx.x * blockDim.x + threadIdx.x;
    if (i >= total4) return;
    const float* src = (sel == 2) ? g_hsum : ext;
    __half* hi = (sel == 0) ? g_xhi : (sel == 1) ? g_hhi : g_shi;
    __half* lo = (sel == 0) ? g_xlo : (sel == 1) ? g_hlo : g_slo;
    if (sel == 0) {
        float4 z = make_float4(0.f, 0.f, 0.f, 0.f);
        reinterpret_cast<float4*>(g_hsum)[i] = z;
        reinterpret_cast<float4*>(g_fcsum)[i] = z;
    }
    float4 v = reinterpret_cast<const float4*>(src)[i];
    float f[4] = {v.x, v.y, v.z, v.w};
    uint32_t hp[2], lp[2];
#pragma unroll
    for (int p = 0; p < 2; p++) {
        __half h0 = __float2half_rn(f[2 * p]);
        __half h1 = __float2half_rn(f[2 * p + 1]);
        __half l0 = __float2half_rn(f[2 * p] - __half2float(h0));
        __half l1 = __float2half_rn(f[2 * p + 1] - __half2float(h1));
        hp[p] = pack2h(h0, h1);
        lp[p] = pack2h(l0, l1);
    }
    reinterpret_cast<uint2*>(hi)[i] = make_uint2(hp[0], hp[1]);
    reinterpret_cast<uint2*>(lo)[i] = make_uint2(lp[0], lp[1]);
}

// ---------------- pack weights: fp32 -> fp16, row-major [n][k] tiles ----------------
__global__ void k_prep(const float* __restrict__ w_iou, const float* __restrict__ w_f,
                       const float* __restrict__ u_iou, const float* __restrict__ u_f,
                       const float* __restrict__ b_iou, const float* __restrict__ b_f) {
    int i = blockIdx.x * blockDim.x + threadIdx.x;
    if (i < 512) g_bias[i] = (i < 384) ? b_iou[i] : b_f[i - 384];
    if (i >= 131072) return;
    int n, k, tile;
    float val;
    if (i < 65536) {                       // [w_iou ; w_f], 512 rows
        n = i >> 7; k = i & 127;
        tile = n >> 7;
        val = (n < 384) ? w_iou[n * 128 + k] : w_f[(n - 384) * 128 + k];
    } else if (i < 65536 + 49152) {        // u_iou, 384 rows
        int j = i - 65536;
        n = j >> 7; k = j & 127;
        tile = 4 + (n >> 7);
        val = u_iou[n * 128 + k];
    } else {                               // u_f, 128 rows
        int j = i - 114688;
        n = j >> 7; k = j & 127;
        tile = 7;
        val = u_f[n * 128 + k];
    }
    g_Bhi[tile * 16384 + (n & 127) * 128 + k] = __float2half_rn(val);
}

// copy one [128][128] fp16 tile, global row-major -> smem padded LDA, via cp.async
__device__ __forceinline__ void copy_tile(uint32_t sdst, const __half* gsrc, int tid) {
#pragma unroll
    for (int it = 0; it < 8; it++) {
        int j = tid + it * 256;        // 2048 16B chunks
        int r = j >> 4, c = j & 15;
        cp16(sdst + (uint32_t)(r * LDA + c * 8) * 2, gsrc + r * 128 + c * 8);
    }
}

// ============================================================================
// fp16 mma.sync GEMM, 2-term split: D = Ahi*Bhi + Alo*Bhi (B fp16 single).
// A row tile [128,128] hi/lo resident; loop over output column tiles with
// double-buffered B. 256 threads, warp grid 4x2, warp tile 32x64 (R6-proven).
// B frags loaded ONCE per kb, reused by both A terms.
// sel 0: x -> g_xall (4 tiles, +bias). sel 1: h -> g_hu. sel 2: hsum -> g_uhsum.
// ============================================================================
__global__ void __launch_bounds__(256) k_mma(int sel) {
    const __half* Ahi = (sel == 0) ? g_xhi : (sel == 1) ? g_hhi : g_shi;
    const __half* Alo = (sel == 0) ? g_xlo : (sel == 1) ? g_hlo : g_slo;
    float* out = (sel == 0) ? g_xall : (sel == 1) ? g_hu : g_uhsum;
    const int ostride = (sel == 0) ? 512 : (sel == 1) ? 128 : 384;
    const int first   = (sel == 0) ? 0 : (sel == 1) ? 7 : 4;
    const int ntiles  = (sel == 0) ? 4 : (sel == 1) ? 1 : 3;
    const int usebias = (sel == 0);

    extern __shared__ __half sm[];
    const int tid = threadIdx.x;
    const int lane = tid & 31, wid = tid >> 5;
    const int brow = blockIdx.x * 128;

    const uint32_t sA32 = smem_u32(sm);          // A hi
    const uint32_t sB32 = sA32 + 2 * TSZ;        // B stage 0; stage 1 at +TSZ

    copy_tile(sA32, Ahi + (size_t)brow * 128, tid);
    copy_tile(sA32 + TSZ, Alo + (size_t)brow * 128, tid);
    copy_tile(sB32, g_Bhi + (size_t)first * 16384, tid);
    cp_commit();

    // ---- warp tiling: 4x2 warps, each 32 rows x 64 cols ----
    const int wr = wid & 3;
    const int wcol = wid >> 2;
    const int aRow = wr * 32 + (lane & 15);
    const int aK   = (lane >> 4) * 8;
    const int gg   = lane >> 3;
    const int bRow = wcol * 64 + (gg >> 1) * 8 + (lane & 7);
    const int bK   = (gg & 1) * 8;
    const uint32_t aHiB = sA32 + (uint32_t)(aRow * LDA + aK) * 2;
    const uint32_t aLoB = aHiB + TSZ;
    const uint32_t bOffB = (uint32_t)(bRow * LDA + bK) * 2;

    for (int t = 0; t < ntiles; t++) {
        if (t + 1 < ntiles) {
            uint32_t st = sB32 + ((t + 1) & 1) * TSZ;
            copy_tile(st, g_Bhi + (size_t)(first + t + 1) * 16384, tid);
            cp_commit();
            cp_wait<1>();
        } else {
            cp_wait<0>();
        }
        __syncthreads();

        const uint32_t bB = sB32 + (t & 1) * TSZ + bOffB;

        float acc[2][8][4];
#pragma unroll
        for (int i = 0; i < 2; i++)
#pragma unroll
            for (int j = 0; j < 8; j++)
#pragma unroll
                for (int q = 0; q < 4; q++) acc[i][j][q] = 0.f;

#pragma unroll
        for (int kb = 0; kb < 8; kb++) {
            uint32_t aH[2][4], aL[2][4];
            ldsm4(aH[0], aHiB + kb * 32);
            ldsm4(aH[1], aHiB + 16 * LDA * 2 + kb * 32);
            ldsm4(aL[0], aLoB + kb * 32);
            ldsm4(aL[1], aLoB + 16 * LDA * 2 + kb * 32);
            uint32_t b[4][4];
#pragma unroll
            for (int p = 0; p < 4; p++)
                ldsm4(b[p], bB + p * 16 * LDA * 2 + kb * 32);
#pragma unroll
            for (int i = 0; i < 2; i++)
#pragma unroll
                for (int j = 0; j < 8; j++) {
                    uint32_t b0 = b[j >> 1][(j & 1) * 2], b1 = b[j >> 1][(j & 1) * 2 + 1];
                    mma16816(acc[i][j], aH[i], b0, b1);
                    mma16816(acc[i][j], aL[i], b0, b1);
                }
        }

        // ---- epilogue for this column tile ----
        const int colb = t * 128 + wcol * 64;
#pragma unroll
        for (int i = 0; i < 2; i++) {
            int row0 = brow + wr * 32 + i * 16 + (lane >> 2);
            int row1 = row0 + 8;
#pragma unroll
            for (int j = 0; j < 8; j++) {
                int col = colb + j * 8 + (lane & 3) * 2;
                float bx = 0.f, by = 0.f;
                if (usebias) { bx = g_bias[col]; by = g_bias[col + 1]; }
                if (row0 < NN) {
                    float2 v = make_float2(acc[i][j][0] + bx, acc[i][j][1] + by);
                    *reinterpret_cast<float2*>(out + (size_t)row0 * ostride + col) = v;
                }
                if (row1 < NN) {
                    float2 v = make_float2(acc[i][j][2] + bx, acc[i][j][3] + by);
                    *reinterpret_cast<float2*>(out + (size_t)row1 * ostride + col) = v;
                }
            }
        }
        __syncthreads();
    }
}

// ---------------- edge pass: one warp per edge, scalar atomics (R6-proven) ----------------
__global__ void k_edge(const float* __restrict__ h_child, const float* __restrict__ c_child,
                       const int* __restrict__ esrc, const int* __restrict__ edst) {
    int idx = blockIdx.x * blockDim.x + threadIdx.x;
    int e = idx >> 5;
    int q = idx & 31;
    if (e >= NE) return;
    int s = esrc[e];
    int d = edst[e];
    float4 h4  = reinterpret_cast<const float4*>(h_child + (size_t)s * HS)[q];
    float4 hu4 = reinterpret_cast<const float4*>(g_hu + (size_t)s * HS)[q];
    float4 c4  = reinterpret_cast<const float4*>(c_child + (size_t)s * HS)[q];
    float4 xf4 = reinterpret_cast<const float4*>(g_xall + (size_t)d * 512 + 384)[q];
    float* hs = g_hsum + (size_t)d * HS + q * 4;
    float* fc = g_fcsum + (size_t)d * HS + q * 4;
    atomicAdd(hs + 0, h4.x); atomicAdd(hs + 1, h4.y);
    atomicAdd(hs + 2, h4.z); atomicAdd(hs + 3, h4.w);
    atomicAdd(fc + 0, sigmoidf(xf4.x + hu4.x) * c4.x);
    atomicAdd(fc + 1, sigmoidf(xf4.y + hu4.y) * c4.y);
    atomicAdd(fc + 2, sigmoidf(xf4.z + hu4.z) * c4.z);
    atomicAdd(fc + 3, sigmoidf(xf4.w + hu4.w) * c4.w);
}

// ---------------- final node update (R6-proven) ----------------
__global__ void k_final(float* __restrict__ out) {
    int idx = blockIdx.x * blockDim.x + threadIdx.x;
    if (idx >= NN * HS) return;
    int n = idx >> 7;
    int j = idx & 127;
    size_t bx = (size_t)n * 512;
    size_t bu = (size_t)n * 384;
    float i_ = sigmoidf(g_xall[bx + j]       + g_uhsum[bu + j]);
    float o_ = sigmoidf(g_xall[bx + 128 + j] + g_uhsum[bu + 128 + j]);
    float u_ = tanhf(   g_xall[bx + 256 + j] + g_uhsum[bu + 256 + j]);
    float c = i_ * u_ + g_fcsum[idx];
    float h = o_ * tanhf(c);
    out[idx] = h;
    out[(size_t)NN * HS + idx] = c;
}

// ============================================================================
extern "C" void kernel_launch(void* const* d_in, const int* in_sizes, int n_in,
                              void* d_out, int out_size) {
    const float* x       = (const float*)d_in[0];
    const float* h_child = (const float*)d_in[1];
    const float* c_child = (const float*)d_in[2];
    const float* w_iou   = (const float*)d_in[3];
    const float* b_iou   = (const float*)d_in[4];
    const float* w_f     = (const float*)d_in[5];
    const float* b_f     = (const float*)d_in[6];
    const float* u_iou   = (const float*)d_in[7];
    const float* u_f     = (const float*)d_in[8];
    const int*   esrc    = (const int*)d_in[9];
    const int*   edst    = (const int*)d_in[10];
    float* out = (float*)d_out;

    static bool configured = false;
    if (!configured) {
        cudaFuncSetAttribute(k_mma, cudaFuncAttributeMaxDynamicSharedMemorySize, SMEM_MMA);
        configured = true;
    }

    const int total4 = NN * HS / 4;
    const int sgrid = (total4 + 255) / 256;

    k_prep<<<131072 / 256, 256>>>(w_iou, w_f, u_iou, u_f, b_iou, b_f);
    k_split<<<sgrid, 256>>>(x, 0);            // also zeroes g_hsum/g_fcsum
    k_split<<<sgrid, 256>>>(h_child, 1);
    k_mma<<<ROW_TILES, 256, SMEM_MMA>>>(0);   // x -> g_xall (i|o|u|xf)
    k_mma<<<ROW_TILES, 256, SMEM_MMA>>>(1);   // h_child -> g_hu
    k_edge<<<(NE * 32) / 256, 256>>>(h_child, c_child, esrc, edst);
    k_split<<<sgrid, 256>>>(nullptr, 2);      // g_hsum -> g_shi/g_slo
    k_mma<<<ROW_TILES, 256, SMEM_MMA>>>(2);   // g_hsum -> g_uhsum
    k_final<<<(NN * HS + 255) / 256, 256>>>(out);
}

// round 11
// speedup vs baseline: 1.4305x; 1.0942x over previous
#include <cuda_runtime.h>
#include <cuda_fp16.h>
#include <cstdint>

#define NN 200000
#define NE 400000
#define HS 128
#define ROW_TILES 1563            // ceil(200000/128)
#define NPAD (ROW_TILES * 128)    // 200064 padded rows

#define TSZ 32768                 // bytes per swizzled [128x128] fp16 tile
#define SMEM_MMA (3 * TSZ)        // A hi/lo + B single buffer = 98304 B -> 2 CTAs/SM

// ---------------- scratch (device globals; no allocs allowed) ----------------
// NOTE: never passed as kernel args from host (host shadow + ATS trap);
// all resolution happens inside device code via `sel`.
__device__ float g_xall[(size_t)NN * 512];   // x@[w_iou;w_f]^T + bias  [N,512] = i|o|u|xf
__device__ float g_hu[(size_t)NN * HS];      // h_child @ u_f^T         [N,128]
__device__ float g_hsum[(size_t)NN * HS];    // segsum(h_child[src])    [N,128]
__device__ float g_fcsum[(size_t)NN * HS];   // segsum(f*c_child[src])  [N,128]
__device__ float g_uhsum[(size_t)NN * 384];  // hsum @ u_iou^T          [N,384]
// pre-split fp16 A operands: A = hi + lo (22-bit effective mantissa)
__device__ __align__(16) __half g_xhi[(size_t)NPAD * HS];
__device__ __align__(16) __half g_xlo[(size_t)NPAD * HS];
__device__ __align__(16) __half g_hhi[(size_t)NPAD * HS];
__device__ __align__(16) __half g_hlo[(size_t)NPAD * HS];
__device__ __align__(16) __half g_shi[(size_t)NPAD * HS];
__device__ __align__(16) __half g_slo[(size_t)NPAD * HS];
// packed fp16 weights (hi only), 8 tiles of [128 n][128 k] row-major:
// tiles 0-3: [w_iou;w_f] (512 rows), 4-6: u_iou (384), 7: u_f (128)
__device__ __align__(16) __half g_Bhi[8 * 16384];
__device__ __align__(16) float g_bias[512];

__device__ __forceinline__ float sigmoidf(float v) { return 1.0f / (1.0f + __expf(-v)); }

__device__ __forceinline__ uint32_t smem_u32(const void* p) {
    uint32_t a;
    asm("{ .reg .u64 t; cvta.to.shared.u64 t, %1; cvt.u32.u64 %0, t; }" : "=r"(a) : "l"(p));
    return a;
}

__device__ __forceinline__ void ldsm4(uint32_t* r, uint32_t addr) {
    asm volatile("ldmatrix.sync.aligned.m8n8.x4.shared.b16 {%0,%1,%2,%3}, [%4];"
                 : "=r"(r[0]), "=r"(r[1]), "=r"(r[2]), "=r"(r[3]) : "r"(addr));
}

__device__ __forceinline__ void mma16816(float* c, const uint32_t* a, uint32_t b0, uint32_t b1) {
    asm volatile(
        "mma.sync.aligned.m16n8k16.row.col.f32.f16.f16.f32 "
        "{%0,%1,%2,%3}, {%4,%5,%6,%7}, {%8,%9}, {%0,%1,%2,%3};"
        : "+f"(c[0]), "+f"(c[1]), "+f"(c[2]), "+f"(c[3])
        : "r"(a[0]), "r"(a[1]), "r"(a[2]), "r"(a[3]), "r"(b0), "r"(b1));
}

__device__ __forceinline__ void cp16(uint32_t dst, const void* src) {
    asm volatile("cp.async.cg.shared.global [%0], [%1], 16;" :: "r"(dst), "l"(src));
}
__device__ __forceinline__ void cp_commit() {
    asm volatile("cp.async.commit_group;");
}
template <int N>
__device__ __forceinline__ void cp_wait() {
    asm volatile("cp.async.wait_group %0;" :: "n"(N));
}

__device__ __forceinline__ uint32_t pack2h(__half lo, __half hi) {
    return (uint32_t)__half_as_ushort(lo) | ((uint32_t)__half_as_ushort(hi) << 16);
}

// ---------------- split fp32 -> fp16 hi/lo (4 elems per thread) ----------------
// sel 0: src=ext (x)       -> g_xhi/g_xlo   (+ zero g_hsum/g_fcsum)
// sel 1: src=ext (h_child) -> g_hhi/g_hlo
// sel 2: src=g_hsum        -> g_shi/g_slo
__global__ void k_split(const float* __restrict__ ext, int sel) {
    const int total4 = NN * HS / 4;
    int i = blockIdx.x * blockDim.x + threadIdx.x;
    if (i >= total4) return;
    const float* src = (sel == 2) ? g_hsum : ext;
    __half* hi = (sel == 0) ? g_xhi : (sel == 1) ? g_hhi : g_shi;
    __half* lo = (sel == 0) ? g_xlo : (sel == 1) ? g_hlo : g_slo;
    if (sel == 0) {
        float4 z = make_float4(0.f, 0.f, 0.f, 0.f);
        reinterpret_cast<float4*>(g_hsum)[i] = z;
        reinterpret_cast<float4*>(g_fcsum)[i] = z;
    }
    float4 v = reinterpret_cast<const float4*>(src)[i];
    float f[4] = {v.x, v.y, v.z, v.w};
    uint32_t hp[2], lp[2];
#pragma unroll
    for (int p = 0; p < 2; p++) {
        __half h0 = __float2half_rn(f[2 * p]);
        __half h1 = __float2half_rn(f[2 * p + 1]);
        __half l0 = __float2half_rn(f[2 * p] - __half2float(h0));
        __half l1 = __float2half_rn(f[2 * p + 1] - __half2float(h1));
        hp[p] = pack2h(h0, h1);
        lp[p] = pack2h(l0, l1);
    }
    reinterpret_cast<uint2*>(hi)[i] = make_uint2(hp[0], hp[1]);
    reinterpret_cast<uint2*>(lo)[i] = make_uint2(lp[0], lp[1]);
}

// ---------------- pack weights: fp32 -> fp16, row-major [n][k] tiles ----------------
__global__ void k_prep(const float* __restrict__ w_iou, const float* __restrict__ w_f,
                       const float* __restrict__ u_iou, const float* __restrict__ u_f,
                       const float* __restrict__ b_iou, const float* __restrict__ b_f) {
    int i = blockIdx.x * blockDim.x + threadIdx.x;
    if (i < 512) g_bias[i] = (i < 384) ? b_iou[i] : b_f[i - 384];
    if (i >= 131072) return;
    int n, k, tile;
    float val;
    if (i < 65536) {                       // [w_iou ; w_f], 512 rows
        n = i >> 7; k = i & 127;
        tile = n >> 7;
        val = (n < 384) ? w_iou[n * 128 + k] : w_f[(n - 384) * 128 + k];
    } else if (i < 65536 + 49152) {        // u_iou, 384 rows
        int j = i - 65536;
        n = j >> 7; k = j & 127;
        tile = 4 + (n >> 7);
        val = u_iou[n * 128 + k];
    } else {                               // u_f, 128 rows
        int j = i - 114688;
        n = j >> 7; k = j & 127;
        tile = 7;
        val = u_f[n * 128 + k];
    }
    g_Bhi[tile * 16384 + (n & 127) * 128 + k] = __float2half_rn(val);
}

// swizzled byte offset of 16B chunk (r, c) in a [128 rows x 16 chunks] tile:
// chunk column XORed with low 3 bits of row -> ldmatrix 8-row access is bank-conflict-free.
__device__ __forceinline__ uint32_t sw_chunk(int r, int c) {
    return (uint32_t)(r * 256 + ((c ^ (r & 7)) << 4));
}

// copy one [128][128] fp16 tile, global row-major -> swizzled smem, via cp.async
__device__ __forceinline__ void copy_tile(uint32_t sdst, const __half* gsrc, int tid) {
#pragma unroll
    for (int it = 0; it < 8; it++) {
        int j = tid + it * 256;        // 2048 16B chunks
        int r = j >> 4, c = j & 15;
        cp16(sdst + sw_chunk(r, c), gsrc + r * 128 + c * 8);
    }
}

// ============================================================================
// fp16 mma.sync GEMM, 2-term split: D = Ahi*Bhi + Alo*Bhi.
// Swizzled 32KB tiles; A hi/lo resident + single B buffer = 96KB -> 2 CTAs/SM.
// B reload per column tile overlaps epilogue stores + co-resident CTA.
// 256 threads, warp grid 4x2, warp tile 32x64.
// sel 0: x -> g_xall (4 tiles, +bias). sel 1: h -> g_hu. sel 2: hsum -> g_uhsum.
// ============================================================================
__global__ void __launch_bounds__(256, 2) k_mma(int sel) {
    const __half* Ahi = (sel == 0) ? g_xhi : (sel == 1) ? g_hhi : g_shi;
    const __half* Alo = (sel == 0) ? g_xlo : (sel == 1) ? g_hlo : g_slo;
    float* out = (sel == 0) ? g_xall : (sel == 1) ? g_hu : g_uhsum;
    const int ostride = (sel == 0) ? 512 : (sel == 1) ? 128 : 384;
    const int first   = (sel == 0) ? 0 : (sel == 1) ? 7 : 4;
    const int ntiles  = (sel == 0) ? 4 : (sel == 1) ? 1 : 3;
    const int usebias = (sel == 0);

    extern __shared__ __half sm[];
    const int tid = threadIdx.x;
    const int lane = tid & 31, wid = tid >> 5;
    const int brow = blockIdx.x * 128;

    const uint32_t sA = smem_u32(sm);            // A hi; lo at +TSZ
    const uint32_t sB = sA + 2 * TSZ;            // single B buffer

    copy_tile(sA, Ahi + (size_t)brow * 128, tid);
    copy_tile(sA + TSZ, Alo + (size_t)brow * 128, tid);
    copy_tile(sB, g_Bhi + (size_t)first * 16384, tid);
    cp_commit();

    // ---- warp tiling: 4x2 warps, each 32 rows x 64 cols ----
    const int wr = wid & 3;
    const int wcol = wid >> 2;
    const int aRow = wr * 32 + (lane & 15);
    const int c0a  = lane >> 4;                 // A chunk base (0 or 1)
    const int rma  = aRow & 7;                  // same for aRow+16 (16 = 0 mod 8)
    const int gg   = lane >> 3;
    const int bRow = wcol * 64 + (gg >> 1) * 8 + (lane & 7);
    const int c0b  = gg & 1;
    const int rmb  = bRow & 7;                  // same for bRow+16p

    const uint32_t aBase0 = sA + (uint32_t)aRow * 256;        // hi, rows [aRow]
    const uint32_t aBase1 = aBase0 + 16 * 256;                // hi, rows [aRow+16]
    const uint32_t bBase  = sB + (uint32_t)bRow * 256;

    for (int t = 0; t < ntiles; t++) {
        cp_wait<0>();
        __syncthreads();                       // B[t] (and A) visible to all

        float acc[2][8][4];
#pragma unroll
        for (int i = 0; i < 2; i++)
#pragma unroll
            for (int j = 0; j < 8; j++)
#pragma unroll
                for (int q = 0; q < 4; q++) acc[i][j][q] = 0.f;

#pragma unroll
        for (int kb = 0; kb < 8; kb++) {
            const uint32_t ca = (uint32_t)(((c0a + 2 * kb) ^ rma) << 4);
            const uint32_t cb = (uint32_t)(((c0b + 2 * kb) ^ rmb) << 4);
            uint32_t aH[2][4], aL[2][4];
            ldsm4(aH[0], aBase0 + ca);
            ldsm4(aH[1], aBase1 + ca);
            ldsm4(aL[0], aBase0 + TSZ + ca);
            ldsm4(aL[1], aBase1 + TSZ + ca);
            uint32_t b[4][4];
#pragma unroll
            for (int p = 0; p < 4; p++)
                ldsm4(b[p], bBase + p * 16 * 256 + cb);
#pragma unroll
            for (int i = 0; i < 2; i++)
#pragma unroll
                for (int j = 0; j < 8; j++) {
                    uint32_t b0 = b[j >> 1][(j & 1) * 2], b1 = b[j >> 1][(j & 1) * 2 + 1];
                    mma16816(acc[i][j], aH[i], b0, b1);
                    mma16816(acc[i][j], aL[i], b0, b1);
                }
        }

        __syncthreads();                       // all warps done reading B[t]
        if (t + 1 < ntiles) {                  // overlap next-B load with epilogue
            copy_tile(sB, g_Bhi + (size_t)(first + t + 1) * 16384, tid);
            cp_commit();
        }

        // ---- epilogue for this column tile ----
        const int colb = t * 128 + wcol * 64;
#pragma unroll
        for (int i = 0; i < 2; i++) {
            int row0 = brow + wr * 32 + i * 16 + (lane >> 2);
            int row1 = row0 + 8;
#pragma unroll
            for (int j = 0; j < 8; j++) {
                int col = colb + j * 8 + (lane & 3) * 2;
                float bx = 0.f, by = 0.f;
                if (usebias) { bx = g_bias[col]; by = g_bias[col + 1]; }
                if (row0 < NN) {
                    float2 v = make_float2(acc[i][j][0] + bx, acc[i][j][1] + by);
                    *reinterpret_cast<float2*>(out + (size_t)row0 * ostride + col) = v;
                }
                if (row1 < NN) {
                    float2 v = make_float2(acc[i][j][2] + bx, acc[i][j][3] + by);
                    *reinterpret_cast<float2*>(out + (size_t)row1 * ostride + col) = v;
                }
            }
        }
    }
}

// ---------------- edge pass: one warp per edge, scalar atomics (R6-proven) ----------------
__global__ void k_edge(const float* __restrict__ h_child, const float* __restrict__ c_child,
                       const int* __restrict__ esrc, const int* __restrict__ edst) {
    int idx = blockIdx.x * blockDim.x + threadIdx.x;
    int e = idx >> 5;
    int q = idx & 31;
    if (e >= NE) return;
    int s = esrc[e];
    int d = edst[e];
    float4 h4  = reinterpret_cast<const float4*>(h_child + (size_t)s * HS)[q];
    float4 hu4 = reinterpret_cast<const float4*>(g_hu + (size_t)s * HS)[q];
    float4 c4  = reinterpret_cast<const float4*>(c_child + (size_t)s * HS)[q];
    float4 xf4 = reinterpret_cast<const float4*>(g_xall + (size_t)d * 512 + 384)[q];
    float* hs = g_hsum + (size_t)d * HS + q * 4;
    float* fc = g_fcsum + (size_t)d * HS + q * 4;
    atomicAdd(hs + 0, h4.x); atomicAdd(hs + 1, h4.y);
    atomicAdd(hs + 2, h4.z); atomicAdd(hs + 3, h4.w);
    atomicAdd(fc + 0, sigmoidf(xf4.x + hu4.x) * c4.x);
    atomicAdd(fc + 1, sigmoidf(xf4.y + hu4.y) * c4.y);
    atomicAdd(fc + 2, sigmoidf(xf4.z + hu4.z) * c4.z);
    atomicAdd(fc + 3, sigmoidf(xf4.w + hu4.w) * c4.w);
}

// ---------------- final node update (R6-proven) ----------------
__global__ void k_final(float* __restrict__ out) {
    int idx = blockIdx.x * blockDim.x + threadIdx.x;
    if (idx >= NN * HS) return;
    int n = idx >> 7;
    int j = idx & 127;
    size_t bx = (size_t)n * 512;
    size_t bu = (size_t)n * 384;
    float i_ = sigmoidf(g_xall[bx + j]       + g_uhsum[bu + j]);
    float o_ = sigmoidf(g_xall[bx + 128 + j] + g_uhsum[bu + 128 + j]);
    float u_ = tanhf(   g_xall[bx + 256 + j] + g_uhsum[bu + 256 + j]);
    float c = i_ * u_ + g_fcsum[idx];
    float h = o_ * tanhf(c);
    out[idx] = h;
    out[(size_t)NN * HS + idx] = c;
}

// ============================================================================
extern "C" void kernel_launch(void* const* d_in, const int* in_sizes, int n_in,
                              void* d_out, int out_size) {
    const float* x       = (const float*)d_in[0];
    const float* h_child = (const float*)d_in[1];
    const float* c_child = (const float*)d_in[2];
    const float* w_iou   = (const float*)d_in[3];
    const float* b_iou   = (const float*)d_in[4];
    const float* w_f     = (const float*)d_in[5];
    const float* b_f     = (const float*)d_in[6];
    const float* u_iou   = (const float*)d_in[7];
    const float* u_f     = (const float*)d_in[8];
    const int*   esrc    = (const int*)d_in[9];
    const int*   edst    = (const int*)d_in[10];
    float* out = (float*)d_out;

    static bool configured = false;
    if (!configured) {
        cudaFuncSetAttribute(k_mma, cudaFuncAttributeMaxDynamicSharedMemorySize, SMEM_MMA);
        configured = true;
    }

    const int total4 = NN * HS / 4;
    const int sgrid = (total4 + 255) / 256;

    k_prep<<<131072 / 256, 256>>>(w_iou, w_f, u_iou, u_f, b_iou, b_f);
    k_split<<<sgrid, 256>>>(x, 0);            // also zeroes g_hsum/g_fcsum
    k_split<<<sgrid, 256>>>(h_child, 1);
    k_mma<<<ROW_TILES, 256, SMEM_MMA>>>(0);   // x -> g_xall (i|o|u|xf)
    k_mma<<<ROW_TILES, 256, SMEM_MMA>>>(1);   // h_child -> g_hu
    k_edge<<<(NE * 32) / 256, 256>>>(h_child, c_child, esrc, edst);
    k_split<<<sgrid, 256>>>(nullptr, 2);      // g_hsum -> g_shi/g_slo
    k_mma<<<ROW_TILES, 256, SMEM_MMA>>>(2);   // g_hsum -> g_uhsum
    k_final<<<(NN * HS + 255) / 256, 256>>>(out);
}